// round 8
// baseline (speedup 1.0000x reference)
#include <cuda_runtime.h>

#define Bb   4
#define Nn   50000
#define Kk   128
#define Ss   256
#define PG   176                // points per chunk
#define NG   285                // ceil(50000/176)
#define GPAD 288                // padded row length for partials (16B-aligned)
#define NBLK (NG * 2)           // 570 scoring blocks
#define EPSF 1e-5f

typedef unsigned long long u64;

__device__ float g_transforms[Bb * Kk * 16];   // scalar 4x4 row-major (output form)
__device__ u64   g_tpacked[Bb * Kk * 12];      // duplicated-pair f32x2 operands
__device__ float g_part[Bb * Kk * GPAD];       // [bk][g] partial sums
__device__ unsigned int g_cnt = 0;

__device__ __forceinline__ u64 pack2(float lo, float hi) {
    u64 r; asm("mov.b64 %0, {%1,%2};" : "=l"(r) : "f"(lo), "f"(hi)); return r;
}
__device__ __forceinline__ void unpack2(u64 v, float& lo, float& hi) {
    asm("mov.b64 {%0,%1}, %2;" : "=f"(lo), "=f"(hi) : "l"(v));
}
__device__ __forceinline__ u64 fma2(u64 a, u64 b, u64 c) {
    u64 d; asm("fma.rn.f32x2 %0, %1, %2, %3;" : "=l"(d) : "l"(a), "l"(b), "l"(c)); return d;
}
__device__ __forceinline__ u64 add2(u64 a, u64 b) {
    u64 d; asm("add.rn.f32x2 %0, %1, %2;" : "=l"(d) : "l"(a), "l"(b)); return d;
}
__device__ __forceinline__ u64 mul2(u64 a, u64 b) {
    u64 d; asm("mul.rn.f32x2 %0, %1, %2;" : "=l"(d) : "l"(a), "l"(b)); return d;
}
__device__ __forceinline__ float frcp(float x)   { float r; asm("rcp.approx.f32 %0,%1;"   : "=f"(r) : "f"(x)); return r; }
__device__ __forceinline__ float fsqrta(float x) { float r; asm("sqrt.approx.f32 %0,%1;"  : "=f"(r) : "f"(x)); return r; }
__device__ __forceinline__ float frsqrt(float x) { float r; asm("rsqrt.approx.f32 %0,%1;" : "=f"(r) : "f"(x)); return r; }

// ---------------------------------------------------------------------------
// Kernel 1: warp-per-hypothesis fit (validated in R5/R7).
// ---------------------------------------------------------------------------
__device__ __forceinline__ float warp_sum(float v) {
#pragma unroll
    for (int o = 16; o; o >>= 1) v += __shfl_xor_sync(0xffffffffu, v, o);
    return v;
}

__global__ void __launch_bounds__(256)
procrustes_fused_kernel(const float* __restrict__ src,
                        const float* __restrict__ tgt,
                        const float* __restrict__ wgt,
                        const int*   __restrict__ sel) {
    int wid = threadIdx.x >> 5, lane = threadIdx.x & 31;
    int h = blockIdx.x * 8 + wid;
    int b = h >> 7, k = h & (Kk - 1);

    float m[16];
#pragma unroll
    for (int q = 0; q < 16; q++) m[q] = 0.f;

#pragma unroll
    for (int j = 0; j < 8; j++) {
        int idx = sel[k * Ss + j * 32 + lane];
        int pb  = (b * Nn + idx) * 3;
        float sx = src[pb + 0], sy = src[pb + 1], sz = src[pb + 2];
        float tx = tgt[pb + 0], ty = tgt[pb + 1], tz = tgt[pb + 2];
        float ww = wgt[b * Nn + idx];
        float wsx = ww * sx, wsy = ww * sy, wsz = ww * sz;
        m[0] += ww;
        m[1] += wsx;      m[2] += wsy;      m[3] += wsz;
        m[4] += ww * tx;  m[5] += ww * ty;  m[6] += ww * tz;
        m[7]  += wsx * tx; m[8]  += wsx * ty; m[9]  += wsx * tz;
        m[10] += wsy * tx; m[11] += wsy * ty; m[12] += wsy * tz;
        m[13] += wsz * tx; m[14] += wsz * ty; m[15] += wsz * tz;
    }
#pragma unroll
    for (int q = 0; q < 16; q++) m[q] = warp_sum(m[q]);

    if (lane == 0) {
        float W    = m[0];
        float invW = 1.0f / (W + EPSF);
        float sig  = W * invW;
        float scx = m[1] * invW, scy = m[2] * invW, scz = m[3] * invW;
        float tcx = m[4] * invW, tcy = m[5] * invW, tcz = m[6] * invW;
        float c2  = 2.0f - sig;
        float Sxx = m[7]  * invW - c2 * scx * tcx;
        float Sxy = m[8]  * invW - c2 * scx * tcy;
        float Sxz = m[9]  * invW - c2 * scx * tcz;
        float Syx = m[10] * invW - c2 * scy * tcx;
        float Syy = m[11] * invW - c2 * scy * tcy;
        float Syz = m[12] * invW - c2 * scy * tcz;
        float Szx = m[13] * invW - c2 * scz * tcx;
        float Szy = m[14] * invW - c2 * scz * tcy;
        float Szz = m[15] * invW - c2 * scz * tcz;

        float A[4][4], V[4][4];
        A[0][0] = Sxx + Syy + Szz; A[0][1] = Syz - Szy; A[0][2] = Szx - Sxz; A[0][3] = Sxy - Syx;
        A[1][1] = Sxx - Syy - Szz; A[1][2] = Sxy + Syx; A[1][3] = Szx + Sxz;
        A[2][2] = -Sxx + Syy - Szz; A[2][3] = Syz + Szy;
        A[3][3] = -Sxx - Syy + Szz;
        A[1][0] = A[0][1]; A[2][0] = A[0][2]; A[3][0] = A[0][3];
        A[2][1] = A[1][2]; A[3][1] = A[1][3]; A[3][2] = A[2][3];
#pragma unroll
        for (int i = 0; i < 4; i++)
#pragma unroll
            for (int j = 0; j < 4; j++) V[i][j] = (i == j) ? 1.f : 0.f;

        for (int sweep = 0; sweep < 6; sweep++) {
#pragma unroll
            for (int p = 0; p < 3; p++) {
#pragma unroll
                for (int q = p + 1; q < 4; q++) {
                    float apq = A[p][q];
                    if (fabsf(apq) > 1e-20f) {
                        float tau = (A[q][q] - A[p][p]) * 0.5f * frcp(apq);
                        float tt  = (tau >= 0.f ? 1.f : -1.f) *
                                    frcp(fabsf(tau) + fsqrta(fmaf(tau, tau, 1.f)));
                        float c = frsqrt(fmaf(tt, tt, 1.f));
                        float sn = tt * c;
#pragma unroll
                        for (int mm = 0; mm < 4; mm++) {
                            float amp = A[mm][p], amq = A[mm][q];
                            A[mm][p] = c * amp - sn * amq;
                            A[mm][q] = sn * amp + c * amq;
                        }
#pragma unroll
                        for (int mm = 0; mm < 4; mm++) {
                            float apm = A[p][mm], aqm = A[q][mm];
                            A[p][mm] = c * apm - sn * aqm;
                            A[q][mm] = sn * apm + c * aqm;
                        }
#pragma unroll
                        for (int mm = 0; mm < 4; mm++) {
                            float vmp = V[mm][p], vmq = V[mm][q];
                            V[mm][p] = c * vmp - sn * vmq;
                            V[mm][q] = sn * vmp + c * vmq;
                        }
                    }
                }
            }
        }
        int jb = 0; float lb = A[0][0];
#pragma unroll
        for (int j = 1; j < 4; j++) { if (A[j][j] > lb) { lb = A[j][j]; jb = j; } }
        float qw = V[0][jb], qx = V[1][jb], qy = V[2][jb], qz = V[3][jb];
        float qn = frsqrt(qw * qw + qx * qx + qy * qy + qz * qz);
        qw *= qn; qx *= qn; qy *= qn; qz *= qn;

        float R00 = 1.f - 2.f * (qy * qy + qz * qz), R01 = 2.f * (qx * qy - qw * qz), R02 = 2.f * (qx * qz + qw * qy);
        float R10 = 2.f * (qx * qy + qw * qz), R11 = 1.f - 2.f * (qx * qx + qz * qz), R12 = 2.f * (qy * qz - qw * qx);
        float R20 = 2.f * (qx * qz - qw * qy), R21 = 2.f * (qy * qz + qw * qx), R22 = 1.f - 2.f * (qx * qx + qy * qy);

        float t0 = tcx - (R00 * scx + R01 * scy + R02 * scz);
        float t1 = tcy - (R10 * scx + R11 * scy + R12 * scz);
        float t2 = tcz - (R20 * scx + R21 * scy + R22 * scz);

        float* T = g_transforms + h * 16;
        T[0] = R00; T[1] = R01; T[2]  = R02; T[3]  = t0;
        T[4] = R10; T[5] = R11; T[6]  = R12; T[7]  = t1;
        T[8] = R20; T[9] = R21; T[10] = R22; T[11] = t2;
        T[12] = 0.f; T[13] = 0.f; T[14] = 0.f; T[15] = 1.f;

        u64* P = g_tpacked + h * 12;
        P[0] = pack2(R00, R00); P[1] = pack2(R01, R01); P[2]  = pack2(R02, R02);
        P[3] = pack2(R10, R10); P[4] = pack2(R11, R11); P[5]  = pack2(R12, R12);
        P[6] = pack2(R20, R20); P[7] = pack2(R21, R21); P[8]  = pack2(R22, R22);
        P[9] = pack2(t0, t0);   P[10] = pack2(t1, t1);  P[11] = pack2(t2, t2);
    }
}

// ---------------------------------------------------------------------------
// Kernel 2: transform-per-thread scoring. Block = (chunk g, batch-pair y).
// Thread = one hypothesis (its 12 packed tf operands live in registers, one
// scalar accumulator). Points staged into smem pair-SoA; inner loop reads
// them via broadcast LDS.128. No block reduction: each thread writes its own
// partial. Fused last-block argmin.
// ---------------------------------------------------------------------------
__global__ void __launch_bounds__(256, 4)
score_pick_kernel(const float* __restrict__ src,
                  const float* __restrict__ tgt,
                  const float* __restrict__ wgt,
                  float* __restrict__ out) {
    int g = blockIdx.x, y = blockIdx.y;
    int tid = threadIdx.x;
    int lane = tid & 31, wp = tid >> 5;
    int s_slot = tid >> 7;            // which of 2 batches in this block
    int k = tid & 127;
    int b = y * 2 + s_slot;
    int bk = b * Kk + k;

    // pair-SoA: [slot][pair][8 u64]: SX SY SZ NX NY NZ WW pad
    __shared__ __align__(16) u64 sP[2 * (PG / 2) * 8];

    // ---- stage 2 x PG points (zero-padded past Nn) ----
    for (int idx = tid; idx < 2 * PG; idx += 256) {
        int ss = idx / PG;
        int i  = idx - ss * PG;
        int pair = i >> 1, hi = i & 1;
        float* f = (float*)&sP[(ss * (PG / 2) + pair) * 8];
        int p = g * PG + i;
        float vx = 0.f, vy = 0.f, vz = 0.f, qx = 0.f, qy = 0.f, qz = 0.f, vw = 0.f;
        if (p < Nn) {
            int bb = y * 2 + ss;
            int pb = (bb * Nn + p) * 3;
            vx = src[pb + 0]; vy = src[pb + 1]; vz = src[pb + 2];
            qx = -tgt[pb + 0]; qy = -tgt[pb + 1]; qz = -tgt[pb + 2];
            vw = wgt[bb * Nn + p];
        }
        f[0 * 2 + hi] = vx; f[1 * 2 + hi] = vy; f[2 * 2 + hi] = vz;
        f[3 * 2 + hi] = qx; f[4 * 2 + hi] = qy; f[5 * 2 + hi] = qz;
        f[6 * 2 + hi] = vw;
    }

    // ---- this thread's packed transform (12 u64) ----
    const ulonglong2* tp = (const ulonglong2*)(g_tpacked + bk * 12);
    ulonglong2 a0 = tp[0], a1 = tp[1], a2 = tp[2], a3 = tp[3], a4 = tp[4], a5 = tp[5];
    u64 M00 = a0.x, M01 = a0.y, M02 = a1.x;
    u64 M10 = a1.y, M11 = a2.x, M12 = a2.y;
    u64 M20 = a3.x, M21 = a3.y, M22 = a4.x;
    u64 T0  = a4.y, T1  = a5.x, T2  = a5.y;

    __syncthreads();

    const u64* myP = sP + s_slot * (PG / 2) * 8;
    float acc = 0.f;
#pragma unroll 4
    for (int pr = 0; pr < PG / 2; pr++) {
        const ulonglong2* pp = (const ulonglong2*)(myP + pr * 8);
        ulonglong2 c0 = pp[0];   // SX SY
        ulonglong2 c1 = pp[1];   // SZ NX
        ulonglong2 c2 = pp[2];   // NY NZ
        ulonglong2 c3 = pp[3];   // WW --
        u64 dx = fma2(M00, c0.x, fma2(M01, c0.y, fma2(M02, c1.x, add2(T0, c1.y))));
        u64 dy = fma2(M10, c0.x, fma2(M11, c0.y, fma2(M12, c1.x, add2(T1, c2.x))));
        u64 dz = fma2(M20, c0.x, fma2(M21, c0.y, fma2(M22, c1.x, add2(T2, c2.y))));
        u64 d2 = fma2(dx, dx, fma2(dy, dy, mul2(dz, dz)));
        float lo, hi2; unpack2(d2, lo, hi2);
        float w0, w1;  unpack2(c3.x, w0, w1);
        acc = fmaf(w0, fsqrta(lo), acc);
        acc = fmaf(w1, fsqrta(hi2), acc);
    }

    g_part[bk * GPAD + g] = acc;

    // ---- last-block argmin + emit ----
    __threadfence();
    __shared__ unsigned s_old;
    if (tid == 0) s_old = atomicAdd(&g_cnt, 1u);
    __syncthreads();
    if (s_old != NBLK - 1) return;
    __threadfence();

    __shared__ float s_err[Bb * Kk];
    for (int r = tid; r < Bb * Kk; r += 256) {
        const float4* row = (const float4*)(g_part + r * GPAD);
        float s0 = 0.f, s1 = 0.f, s2 = 0.f, s3 = 0.f;
        for (int j = 0; j < NG / 4; j++) {            // 71 float4 = g 0..283
            float4 v = __ldcg(&row[j]);
            s0 += v.x; s1 += v.y; s2 += v.z; s3 += v.w;
        }
        float sum = (s0 + s1) + (s2 + s3);
        sum += __ldcg(&g_part[r * GPAD + (NG - 1)]);  // g = 284
        s_err[r] = sum;
    }
    __syncthreads();

    if (wp < Bb) {   // warp wp handles batch wp
        int bb = wp;
        float best = 1e30f; int bi = 0;
#pragma unroll
        for (int r = 0; r < 4; r++) {
            int kk = r * 32 + lane;
            float v = s_err[bb * Kk + kk];
            if (v < best) { best = v; bi = kk; }
        }
#pragma unroll
        for (int o = 16; o; o >>= 1) {
            float oe = __shfl_xor_sync(0xffffffffu, best, o);
            int   oi = __shfl_xor_sync(0xffffffffu, bi, o);
            if (oe < best || (oe == best && oi < bi)) { best = oe; bi = oi; }
        }
        int bsel = bb * Kk + __shfl_sync(0xffffffffu, bi, 0);
        if (lane < 16)
            out[bb * 16 + lane] = __ldcg(&g_transforms[bsel * 16 + lane]);
    }
    if (tid == 0) g_cnt = 0;   // reset for next graph replay
}

// ---------------------------------------------------------------------------
extern "C" void kernel_launch(void* const* d_in, const int* in_sizes, int n_in,
                              void* d_out, int out_size) {
    const float* src = (const float*)d_in[0];
    const float* tgt = (const float*)d_in[1];
    const float* wgt = (const float*)d_in[2];
    const int*   sel = (const int*)d_in[3];
    float* out = (float*)d_out;

    procrustes_fused_kernel<<<64, 256>>>(src, tgt, wgt, sel);
    dim3 grid2(NG, 2);
    score_pick_kernel<<<grid2, 256>>>(src, tgt, wgt, out);
}